// round 15
// baseline (speedup 1.0000x reference)
#include <cuda_runtime.h>
#include <cuda_fp16.h>
#include <cstdint>

#define NN   12288
#define KK   32
#define DD   128

typedef unsigned long long ull;

// Scratch: G = raw_features @ W_lin^T, fp16 (N x 128, 3.15 MB)
__device__ __align__(16) __half g_Gh[NN * DD];
// Scratch: masked gather weights w[b][k] (1.5 MB)
__device__ __align__(16) float  g_w[NN * KK];

// ---------------------------------------------------------------------------
// helpers
// ---------------------------------------------------------------------------
__device__ __forceinline__ ull pack_dup(float x) {
    ull r;
    asm("mov.b64 %0, {%1, %1};" : "=l"(r) : "f"(x));
    return r;
}
__device__ __forceinline__ void fma2(ull& d, ull a, ull b) {
    asm("fma.rn.f32x2 %0, %1, %2, %0;" : "+l"(d) : "l"(a), "l"(b));
}
__device__ __forceinline__ void unpack2(float& lo, float& hi, ull v) {
    asm("mov.b64 {%0, %1}, %2;" : "=f"(lo), "=f"(hi) : "l"(v));
}
__device__ __forceinline__ unsigned smem_u32(const void* p) {
    unsigned r;
    asm("{ .reg .u64 t; cvta.to.shared.u64 t, %1; cvt.u32.u64 %0, t; }"
        : "=r"(r) : "l"(p));
    return r;
}

// ---------------------------------------------------------------------------
// Kernel A (main stream, placed first): G = F @ W^T via HMMA
// (mma.sync.m16n8k16, f16 in / f32 acc, fp16 out). 96 CTAs x 256 thr;
// CTA = 128 rows x 128 cols x K=128. Tiny footprint: tensor pipe, 24.5K
// threads total, 9.4 MB traffic — orthogonal to wprep on every resource axis.
// ---------------------------------------------------------------------------
__global__ void __launch_bounds__(256)
gemm_hmma_kernel(const float* __restrict__ F, const float* __restrict__ W)
{
    extern __shared__ __half sh[];
    __half* Ah = sh;                  // [128][136]
    __half* Bh = sh + 128 * 136;      // [128][136]   Bh[k][n] = W[n][k]

    const int tid = threadIdx.x;
    const int bm  = blockIdx.x;
    const float* Fblk = F + (size_t)bm * 128 * DD;

    #pragma unroll
    for (int i = 0; i < 16; i++) {
        const int flat = (tid + i * 256) * 4;
        const int r = flat >> 7, c = flat & 127;
        const float4 v = *reinterpret_cast<const float4*>(&Fblk[flat]);
        __half2 h0 = __floats2half2_rn(v.x, v.y);
        __half2 h1 = __floats2half2_rn(v.z, v.w);
        uint2 st;
        st.x = *reinterpret_cast<unsigned*>(&h0);
        st.y = *reinterpret_cast<unsigned*>(&h1);
        *reinterpret_cast<uint2*>(&Ah[r * 136 + c]) = st;
    }
    #pragma unroll
    for (int i = 0; i < 16; i++) {
        const int flat = (tid + i * 256) * 4;
        const int n = flat >> 7, k = flat & 127;
        const float4 v = *reinterpret_cast<const float4*>(&W[flat]);
        Bh[(k + 0) * 136 + n] = __float2half_rn(v.x);
        Bh[(k + 1) * 136 + n] = __float2half_rn(v.y);
        Bh[(k + 2) * 136 + n] = __float2half_rn(v.z);
        Bh[(k + 3) * 136 + n] = __float2half_rn(v.w);
    }
    __syncthreads();

    const int wid  = tid >> 5;
    const int lane = tid & 31;
    const int m0   = wid * 16;

    float acc[16][4];
    #pragma unroll
    for (int j = 0; j < 16; j++)
        #pragma unroll
        for (int t = 0; t < 4; t++)
            acc[j][t] = 0.0f;

    const unsigned aAddr0 = smem_u32(Ah);
    const unsigned bAddr0 = smem_u32(Bh);
    const int l15 = lane & 15;

    #pragma unroll
    for (int kc = 0; kc < 8; kc++) {
        const int k0 = kc * 16;
        unsigned pa = aAddr0 +
            ((m0 + l15) * 136 + k0 + ((lane >> 4) << 3)) * 2;
        unsigned a0, a1, a2, a3;
        asm volatile("ldmatrix.sync.aligned.m8n8.x4.shared.b16 {%0,%1,%2,%3}, [%4];"
                     : "=r"(a0), "=r"(a1), "=r"(a2), "=r"(a3) : "r"(pa));

        #pragma unroll
        for (int j = 0; j < 16; j++) {
            unsigned pb = bAddr0 + ((k0 + l15) * 136 + 8 * j) * 2;
            unsigned b0, b1;
            asm volatile("ldmatrix.sync.aligned.m8n8.x2.trans.shared.b16 {%0,%1}, [%2];"
                         : "=r"(b0), "=r"(b1) : "r"(pb));
            asm volatile(
                "mma.sync.aligned.m16n8k16.row.col.f32.f16.f16.f32 "
                "{%0,%1,%2,%3}, {%4,%5,%6,%7}, {%8,%9}, {%0,%1,%2,%3};"
                : "+f"(acc[j][0]), "+f"(acc[j][1]),
                  "+f"(acc[j][2]), "+f"(acc[j][3])
                : "r"(a0), "r"(a1), "r"(a2), "r"(a3), "r"(b0), "r"(b1));
        }
    }

    const int grow = bm * 128 + m0 + (lane >> 2);
    const int coff = (lane & 3) * 2;
    #pragma unroll
    for (int j = 0; j < 16; j++) {
        __half2 lo = __floats2half2_rn(acc[j][0], acc[j][1]);
        __half2 hi = __floats2half2_rn(acc[j][2], acc[j][3]);
        *reinterpret_cast<__half2*>(&g_Gh[(size_t)grow * DD + 8 * j + coff]) = lo;
        *reinterpret_cast<__half2*>(&g_Gh[(size_t)(grow + 8) * DD + 8 * j + coff]) = hi;
    }
}

// ---------------------------------------------------------------------------
// Kernel B (side stream, concurrent with A): w-prep at max TLP.
// 1536 blocks x 256 thr, 1 entry/thread; blocks retire after one load
// round-trip, continuously freeing slots. DRAM-random bound (~14us, 3% issue).
// ---------------------------------------------------------------------------
__global__ void __launch_bounds__(256)
wprep_kernel(const int* __restrict__ nodes,
             const int* __restrict__ neighbors,
             const float* __restrict__ rew)
{
    const int e    = blockIdx.x * 256 + threadIdx.x;   // entry = b*32 + k
    const int node = __ldg(&nodes[e >> 5]);            // warp-broadcast
    const int nb   = __ldg(&neighbors[e]);             // coalesced
    float w = 0.0f;
    if (nb != node)
        w = __ldg(&rew[(size_t)node * NN + nb]);       // random line fill
    g_w[e] = w;                                        // coalesced
}

// ---------------------------------------------------------------------------
// Kernel C (after join): out[b][d] = relu( sum_k w[b][k]*G[nb[b][k]][d] + b )
// 256 thr = 16 nodes/block; warp = 2 nodes, lane owns 8 fp16 cols (LDG.128),
// packed f32x2 accumulate. g_w / g_Gh are L2-warm in the timed loop.
// ---------------------------------------------------------------------------
__global__ void __launch_bounds__(256)
gather_kernel(const int* __restrict__ neighbors,
              const float* __restrict__ b_lin,
              float* __restrict__ out)
{
    __shared__ int   nb_s[16][KK];
    __shared__ float w_s [16][KK];

    const int tid = threadIdx.x;
    const int b0  = blockIdx.x * 16;

    #pragma unroll
    for (int i = 0; i < 2; i++) {
        const int e  = tid + i * 256;
        const int ln = e >> 5;
        const int k  = e & 31;
        const int gi = (b0 + ln) * KK + k;
        nb_s[ln][k] = neighbors[gi];
        w_s [ln][k] = g_w[gi];
    }
    __syncthreads();

    const int lane = tid & 31;
    const int ln2  = ((tid >> 5) << 1) | (lane >> 4);  // local node 0..15
    const int col  = (lane & 15) * 8;                  // 8 cols per lane
    const int b    = b0 + ln2;

    ull acc[4];
    #pragma unroll
    for (int i = 0; i < 4; i++) acc[i] = 0ULL;

    #pragma unroll
    for (int kb = 0; kb < KK; kb += 4) {
        uint4 g[4];
        float wv[4];
        #pragma unroll
        for (int u = 0; u < 4; u++) {
            const int nb = nb_s[ln2][kb + u];
            wv[u] = w_s[ln2][kb + u];
            g[u]  = __ldg(reinterpret_cast<const uint4*>(
                              &g_Gh[(size_t)nb * DD + col]));
        }
        #pragma unroll
        for (int u = 0; u < 4; u++) {
            const ull wd = pack_dup(wv[u]);
            float2 f0 = __half22float2(*reinterpret_cast<__half2*>(&g[u].x));
            float2 f1 = __half22float2(*reinterpret_cast<__half2*>(&g[u].y));
            float2 f2 = __half22float2(*reinterpret_cast<__half2*>(&g[u].z));
            float2 f3 = __half22float2(*reinterpret_cast<__half2*>(&g[u].w));
            fma2(acc[0], wd, *reinterpret_cast<ull*>(&f0));
            fma2(acc[1], wd, *reinterpret_cast<ull*>(&f1));
            fma2(acc[2], wd, *reinterpret_cast<ull*>(&f2));
            fma2(acc[3], wd, *reinterpret_cast<ull*>(&f3));
        }
    }

    float a[8];
    #pragma unroll
    for (int i = 0; i < 4; i++) unpack2(a[2 * i], a[2 * i + 1], acc[i]);

    const float4 bias0 = __ldg(reinterpret_cast<const float4*>(&b_lin[col]));
    const float4 bias1 = __ldg(reinterpret_cast<const float4*>(&b_lin[col + 4]));
    float4 o0, o1;
    o0.x = fmaxf(a[0] + bias0.x, 0.f);
    o0.y = fmaxf(a[1] + bias0.y, 0.f);
    o0.z = fmaxf(a[2] + bias0.z, 0.f);
    o0.w = fmaxf(a[3] + bias0.w, 0.f);
    o1.x = fmaxf(a[4] + bias1.x, 0.f);
    o1.y = fmaxf(a[5] + bias1.y, 0.f);
    o1.z = fmaxf(a[6] + bias1.z, 0.f);
    o1.w = fmaxf(a[7] + bias1.w, 0.f);
    float* op = &out[(size_t)b * DD + col];
    *reinterpret_cast<float4*>(op)     = o0;
    *reinterpret_cast<float4*>(op + 4) = o1;
}

// ---------------------------------------------------------------------------
// Launch: HMMA GEMM (main, placed first — 96 small tensor CTAs) concurrent
// with wprep (side stream, low priority, backfills remaining slots).
// Join, then gather. Streams/events created lazily on the first
// (uncaptured correctness) call; the captured graph holds the fork/join DAG.
//
// Inputs: nodes(i32 N), neighbors(i32 N*K), raw_features(f32 N*128),
//         reweighted(f32 N*N), W_lin(f32 128*128), b_lin(f32 128)
// ---------------------------------------------------------------------------
extern "C" void kernel_launch(void* const* d_in, const int* in_sizes, int n_in,
                              void* d_out, int out_size)
{
    const int*   nodes      = (const int*)  d_in[0];
    const int*   neighbors  = (const int*)  d_in[1];
    const float* raw_feats  = (const float*)d_in[2];
    const float* reweighted = (const float*)d_in[3];
    const float* W_lin      = (const float*)d_in[4];
    const float* b_lin      = (const float*)d_in[5];
    float*       out        = (float*)d_out;

    const int smem = 2 * 128 * 136 * (int)sizeof(__half);  // 69632 B

    static cudaStream_t s_side = nullptr;
    static cudaEvent_t  e_fork = nullptr, e_join = nullptr;
    if (s_side == nullptr) {
        int lo = 0, hi = 0;
        cudaDeviceGetStreamPriorityRange(&lo, &hi);   // lo = lowest priority
        cudaStreamCreateWithPriority(&s_side, cudaStreamNonBlocking, lo);
        cudaEventCreateWithFlags(&e_fork, cudaEventDisableTiming);
        cudaEventCreateWithFlags(&e_join, cudaEventDisableTiming);
        cudaFuncSetAttribute(gemm_hmma_kernel,
                             cudaFuncAttributeMaxDynamicSharedMemorySize, smem);
    }

    // fork side stream into the DAG
    cudaEventRecord(e_fork, 0);
    cudaStreamWaitEvent(s_side, e_fork, 0);

    // A: HMMA GEMM on main stream — 96 CTAs place immediately
    gemm_hmma_kernel<<<NN / 128, 256, smem>>>(raw_feats, W_lin);

    // B: wprep on low-priority side stream — backfills, DRAM-random bound
    wprep_kernel<<<NN * KK / 256, 256, 0, s_side>>>(nodes, neighbors,
                                                    reweighted);
    cudaEventRecord(e_join, s_side);

    // join: gather needs g_w (B) and g_Gh (A)
    cudaStreamWaitEvent(0, e_join, 0);
    gather_kernel<<<NN / 16, 256>>>(neighbors, b_lin, out);
}

// round 16
// speedup vs baseline: 1.0224x; 1.0224x over previous
#include <cuda_runtime.h>
#include <cuda_fp16.h>
#include <cstdint>

#define NN   12288
#define KK   32
#define DD   128

typedef unsigned long long ull;

// Scratch: G = raw_features @ W_lin^T, fp16 (N x 128, 3.15 MB)
__device__ __align__(16) __half g_Gh[NN * DD];
// Scratch: masked gather weights w[b][k] (1.5 MB)
__device__ __align__(16) float  g_w[NN * KK];

// ---------------------------------------------------------------------------
// helpers
// ---------------------------------------------------------------------------
__device__ __forceinline__ ull pack_dup(float x) {
    ull r;
    asm("mov.b64 %0, {%1, %1};" : "=l"(r) : "f"(x));
    return r;
}
__device__ __forceinline__ void fma2(ull& d, ull a, ull b) {
    asm("fma.rn.f32x2 %0, %1, %2, %0;" : "+l"(d) : "l"(a), "l"(b));
}
__device__ __forceinline__ void unpack2(float& lo, float& hi, ull v) {
    asm("mov.b64 {%0, %1}, %2;" : "=f"(lo), "=f"(hi) : "l"(v));
}
__device__ __forceinline__ unsigned smem_u32(const void* p) {
    unsigned r;
    asm("{ .reg .u64 t; cvta.to.shared.u64 t, %1; cvt.u32.u64 %0, t; }"
        : "=r"(r) : "l"(p));
    return r;
}

// ---------------------------------------------------------------------------
// Kernel 1: G = F @ W^T via HMMA (mma.sync.m16n8k16, f16 in / f32 acc,
// fp16 out). 96 CTAs x 256 thr; CTA = 128x128xK=128.  (measured 4.9us)
// ---------------------------------------------------------------------------
__global__ void __launch_bounds__(256)
gemm_hmma_kernel(const float* __restrict__ F, const float* __restrict__ W)
{
    extern __shared__ __half sh[];
    __half* Ah = sh;                  // [128][136]
    __half* Bh = sh + 128 * 136;      // [128][136]   Bh[k][n] = W[n][k]

    const int tid = threadIdx.x;
    const int bm  = blockIdx.x;
    const float* Fblk = F + (size_t)bm * 128 * DD;

    #pragma unroll
    for (int i = 0; i < 16; i++) {
        const int flat = (tid + i * 256) * 4;
        const int r = flat >> 7, c = flat & 127;
        const float4 v = *reinterpret_cast<const float4*>(&Fblk[flat]);
        __half2 h0 = __floats2half2_rn(v.x, v.y);
        __half2 h1 = __floats2half2_rn(v.z, v.w);
        uint2 st;
        st.x = *reinterpret_cast<unsigned*>(&h0);
        st.y = *reinterpret_cast<unsigned*>(&h1);
        *reinterpret_cast<uint2*>(&Ah[r * 136 + c]) = st;
    }
    #pragma unroll
    for (int i = 0; i < 16; i++) {
        const int flat = (tid + i * 256) * 4;
        const int n = flat >> 7, k = flat & 127;
        const float4 v = *reinterpret_cast<const float4*>(&W[flat]);
        Bh[(k + 0) * 136 + n] = __float2half_rn(v.x);
        Bh[(k + 1) * 136 + n] = __float2half_rn(v.y);
        Bh[(k + 2) * 136 + n] = __float2half_rn(v.z);
        Bh[(k + 3) * 136 + n] = __float2half_rn(v.w);
    }
    __syncthreads();

    const int wid  = tid >> 5;
    const int lane = tid & 31;
    const int m0   = wid * 16;

    float acc[16][4];
    #pragma unroll
    for (int j = 0; j < 16; j++)
        #pragma unroll
        for (int t = 0; t < 4; t++)
            acc[j][t] = 0.0f;

    const unsigned aAddr0 = smem_u32(Ah);
    const unsigned bAddr0 = smem_u32(Bh);
    const int l15 = lane & 15;

    #pragma unroll
    for (int kc = 0; kc < 8; kc++) {
        const int k0 = kc * 16;
        unsigned pa = aAddr0 +
            ((m0 + l15) * 136 + k0 + ((lane >> 4) << 3)) * 2;
        unsigned a0, a1, a2, a3;
        asm volatile("ldmatrix.sync.aligned.m8n8.x4.shared.b16 {%0,%1,%2,%3}, [%4];"
                     : "=r"(a0), "=r"(a1), "=r"(a2), "=r"(a3) : "r"(pa));

        #pragma unroll
        for (int j = 0; j < 16; j++) {
            unsigned pb = bAddr0 + ((k0 + l15) * 136 + 8 * j) * 2;
            unsigned b0, b1;
            asm volatile("ldmatrix.sync.aligned.m8n8.x2.trans.shared.b16 {%0,%1}, [%2];"
                         : "=r"(b0), "=r"(b1) : "r"(pb));
            asm volatile(
                "mma.sync.aligned.m16n8k16.row.col.f32.f16.f16.f32 "
                "{%0,%1,%2,%3}, {%4,%5,%6,%7}, {%8,%9}, {%0,%1,%2,%3};"
                : "+f"(acc[j][0]), "+f"(acc[j][1]),
                  "+f"(acc[j][2]), "+f"(acc[j][3])
                : "r"(a0), "r"(a1), "r"(a2), "r"(a3), "r"(b0), "r"(b1));
        }
    }

    const int grow = bm * 128 + m0 + (lane >> 2);
    const int coff = (lane & 3) * 2;
    #pragma unroll
    for (int j = 0; j < 16; j++) {
        __half2 lo = __floats2half2_rn(acc[j][0], acc[j][1]);
        __half2 hi = __floats2half2_rn(acc[j][2], acc[j][3]);
        *reinterpret_cast<__half2*>(&g_Gh[(size_t)grow * DD + 8 * j + coff]) = lo;
        *reinterpret_cast<__half2*>(&g_Gh[(size_t)(grow + 8) * DD + 8 * j + coff]) = hi;
    }
}

// ---------------------------------------------------------------------------
// Kernel 2: w-prep, max TLP, SECTOR-GRANULAR random loads.
// __ldcg (L2-only) + cudaLimitMaxL2FetchGranularity=32 (set host-side) should
// cut the random fill from 128B/access to 32B/access: 48MB -> ~13MB.
// ---------------------------------------------------------------------------
__global__ void __launch_bounds__(256)
wprep_kernel(const int* __restrict__ nodes,
             const int* __restrict__ neighbors,
             const float* __restrict__ rew)
{
    const int e    = blockIdx.x * 256 + threadIdx.x;   // entry = b*32 + k
    const int node = __ldg(&nodes[e >> 5]);            // warp-broadcast
    const int nb   = __ldg(&neighbors[e]);             // coalesced
    float w = 0.0f;
    if (nb != node)
        w = __ldcg(&rew[(size_t)node * NN + nb]);      // L2-only, 32B sector
    g_w[e] = w;                                        // coalesced
}

// ---------------------------------------------------------------------------
// Kernel 3: out[b][d] = relu( sum_k w[b][k]*G[nb[b][k]][d] + bias[d] )
// 256 thr = 16 nodes/block; warp = 2 nodes, lane owns 8 fp16 cols (LDG.128),
// packed f32x2 accumulate. (measured ~6.4us warm)
// ---------------------------------------------------------------------------
__global__ void __launch_bounds__(256)
gather_kernel(const int* __restrict__ neighbors,
              const float* __restrict__ b_lin,
              float* __restrict__ out)
{
    __shared__ int   nb_s[16][KK];
    __shared__ float w_s [16][KK];

    const int tid = threadIdx.x;
    const int b0  = blockIdx.x * 16;

    #pragma unroll
    for (int i = 0; i < 2; i++) {
        const int e  = tid + i * 256;
        const int ln = e >> 5;
        const int k  = e & 31;
        const int gi = (b0 + ln) * KK + k;
        nb_s[ln][k] = neighbors[gi];
        w_s [ln][k] = g_w[gi];
    }
    __syncthreads();

    const int lane = tid & 31;
    const int ln2  = ((tid >> 5) << 1) | (lane >> 4);  // local node 0..15
    const int col  = (lane & 15) * 8;                  // 8 cols per lane
    const int b    = b0 + ln2;

    ull acc[4];
    #pragma unroll
    for (int i = 0; i < 4; i++) acc[i] = 0ULL;

    #pragma unroll
    for (int kb = 0; kb < KK; kb += 4) {
        uint4 g[4];
        float wv[4];
        #pragma unroll
        for (int u = 0; u < 4; u++) {
            const int nb = nb_s[ln2][kb + u];
            wv[u] = w_s[ln2][kb + u];
            g[u]  = __ldg(reinterpret_cast<const uint4*>(
                              &g_Gh[(size_t)nb * DD + col]));
        }
        #pragma unroll
        for (int u = 0; u < 4; u++) {
            const ull wd = pack_dup(wv[u]);
            float2 f0 = __half22float2(*reinterpret_cast<__half2*>(&g[u].x));
            float2 f1 = __half22float2(*reinterpret_cast<__half2*>(&g[u].y));
            float2 f2 = __half22float2(*reinterpret_cast<__half2*>(&g[u].z));
            float2 f3 = __half22float2(*reinterpret_cast<__half2*>(&g[u].w));
            fma2(acc[0], wd, *reinterpret_cast<ull*>(&f0));
            fma2(acc[1], wd, *reinterpret_cast<ull*>(&f1));
            fma2(acc[2], wd, *reinterpret_cast<ull*>(&f2));
            fma2(acc[3], wd, *reinterpret_cast<ull*>(&f3));
        }
    }

    float a[8];
    #pragma unroll
    for (int i = 0; i < 4; i++) unpack2(a[2 * i], a[2 * i + 1], acc[i]);

    const float4 bias0 = __ldg(reinterpret_cast<const float4*>(&b_lin[col]));
    const float4 bias1 = __ldg(reinterpret_cast<const float4*>(&b_lin[col + 4]));
    float4 o0, o1;
    o0.x = fmaxf(a[0] + bias0.x, 0.f);
    o0.y = fmaxf(a[1] + bias0.y, 0.f);
    o0.z = fmaxf(a[2] + bias0.z, 0.f);
    o0.w = fmaxf(a[3] + bias0.w, 0.f);
    o1.x = fmaxf(a[4] + bias1.x, 0.f);
    o1.y = fmaxf(a[5] + bias1.y, 0.f);
    o1.z = fmaxf(a[6] + bias1.z, 0.f);
    o1.w = fmaxf(a[7] + bias1.w, 0.f);
    float* op = &out[(size_t)b * DD + col];
    *reinterpret_cast<float4*>(op)     = o0;
    *reinterpret_cast<float4*>(op + 4) = o1;
}

// ---------------------------------------------------------------------------
// Launch: strictly serial (overlap proven harmful in R9/11/12/13/15).
// One-time device hint (uncaptured first call): cap L2 fetch granularity at
// 32B so random rew misses fill sectors, not 128B lines.
//
// Inputs: nodes(i32 N), neighbors(i32 N*K), raw_features(f32 N*128),
//         reweighted(f32 N*N), W_lin(f32 128*128), b_lin(f32 128)
// ---------------------------------------------------------------------------
extern "C" void kernel_launch(void* const* d_in, const int* in_sizes, int n_in,
                              void* d_out, int out_size)
{
    const int*   nodes      = (const int*)  d_in[0];
    const int*   neighbors  = (const int*)  d_in[1];
    const float* raw_feats  = (const float*)d_in[2];
    const float* reweighted = (const float*)d_in[3];
    const float* W_lin      = (const float*)d_in[4];
    const float* b_lin      = (const float*)d_in[5];
    float*       out        = (float*)d_out;

    const int smem = 2 * 128 * 136 * (int)sizeof(__half);  // 69632 B
    static bool init_done = false;
    if (!init_done) {
        cudaFuncSetAttribute(gemm_hmma_kernel,
                             cudaFuncAttributeMaxDynamicSharedMemorySize, smem);
        // Persistent device hint; set on the uncaptured correctness call only.
        cudaDeviceSetLimit(cudaLimitMaxL2FetchGranularity, 32);
        init_done = true;
    }

    gemm_hmma_kernel<<<NN / 128, 256, smem>>>(raw_feats, W_lin);
    wprep_kernel<<<NN * KK / 256, 256>>>(nodes, neighbors, reweighted);
    gather_kernel<<<NN / 16, 256>>>(neighbors, b_lin, out);
}